// round 9
// baseline (speedup 1.0000x reference)
#include <cuda_runtime.h>
#include <cuda_fp16.h>

#define D      128
#define NMAX   50000
#define EMAX   600000

// Scratch (device globals: allocation-free per harness rules)
__device__ __half g_hh[NMAX * D];    // h = x @ W (UNscaled), fp16
__device__ __half g_xh[NMAX * D];    // layer output ping buffer, fp16
__device__ float  g_dinv[NMAX];
__device__ int    g_cnt[NMAX];
__device__ int    g_off[NMAX];
__device__ int    g_end[NMAX];
__device__ int    g_cur[NMAX];
__device__ int    g_total;
__device__ int    g_col[EMAX];       // CSR (by dst) column = src ids
__device__ int    g_is64;            // edge_index dtype flag (1 = int64)
__device__ __half g_Wht[3][D * D];   // W^T fp16  [layer][n][k]

__device__ __forceinline__ int load_idx(const void* buf, int i) {
    if (g_is64) return (int)((const long long*)buf)[i];
    return ((const int*)buf)[i];
}

// ---------------------------------------------------------------- init: zero cnt + dtype probe
__global__ void init_kernel(const int* __restrict__ w, int N) {
    int i = blockIdx.x * 256 + threadIdx.x;
    if (i < N) g_cnt[i] = 0;
    if (blockIdx.x == 0) {
        int bad = (w[2 * threadIdx.x + 1] != 0) ? 1 : 0;  // 256 odd words
        int any = __syncthreads_or(bad);
        if (threadIdx.x == 0) { g_is64 = !any; g_total = 0; }
    }
}

// ---------------------------------------------------------------- CSR build
__global__ void count_kernel(const void* __restrict__ ei, int E) {
    int e = blockIdx.x * blockDim.x + threadIdx.x;
    if (e < E) atomicAdd(&g_cnt[load_idx(ei, E + e)], 1);
}

// Unordered offset assignment: each node grabs a private contiguous range.
__global__ void offsets_kernel(int N) {
    int i = blockIdx.x * 256 + threadIdx.x;
    if (i >= N) return;
    int c = g_cnt[i];
    int off = atomicAdd(&g_total, c);
    g_off[i] = off;
    g_end[i] = off + c;
    g_cur[i] = off;
    g_dinv[i] = rsqrtf((float)(c + 1));       // +1 self-loop
}

__global__ void fill_kernel(const void* __restrict__ ei, int E) {
    int e = blockIdx.x * blockDim.x + threadIdx.x;
    if (e < E) {
        int dst = load_idx(ei, E + e);
        int src = load_idx(ei, e);
        int p = atomicAdd(&g_cur[dst], 1);
        g_col[p] = src;
    }
}

// ---------------------------------------------------------------- W convert (all 3 layers)
// W [k][n] fp32 -> W^T [n][k] fp16.
__global__ void wsplit_kernel(const float* __restrict__ W1,
                              const float* __restrict__ W2,
                              const float* __restrict__ W3) {
    int idx = blockIdx.x * blockDim.x + threadIdx.x;
    if (idx >= 3 * D * D) return;
    int l = idx >> 14;
    int r = idx & (D * D - 1);
    const float* W = (l == 0) ? W1 : (l == 1) ? W2 : W3;
    int k = r >> 7, n = r & 127;
    g_Wht[l][n * D + k] = __float2half(W[r]);
}

// ---------------------------------------------------------------- Tensor GEMM
// H[m][n] = fp16( sum_k relu?(X[m][k]) * W[k][n] )      (no dinv here!)
// Block tile 64(M) x 128(N), full K=128 in smem. 256 thr = 8 warps, 1 MMA term.
// MODE 0: X fp32 -> convert to fp16 on load; MODE 1: X fp16.
#define APAD   8
#define AROW   (D + APAD)                 // 136 fp16 per padded row
#define SM_AH  0
#define SM_WH  (64 * AROW * 2)
#define SM_TOT (SM_WH + D * AROW * 2)     // 52224 bytes

__device__ __forceinline__ void mma_f16(
    float& c0, float& c1, float& c2, float& c3,
    unsigned a0, unsigned a1, unsigned a2, unsigned a3,
    unsigned b0, unsigned b1)
{
    asm volatile(
        "mma.sync.aligned.m16n8k16.row.col.f32.f16.f16.f32 "
        "{%0,%1,%2,%3}, {%4,%5,%6,%7}, {%8,%9}, {%0,%1,%2,%3};\n"
        : "+f"(c0), "+f"(c1), "+f"(c2), "+f"(c3)
        : "r"(a0), "r"(a1), "r"(a2), "r"(a3), "r"(b0), "r"(b1));
}

template<int MODE>
__global__ void __launch_bounds__(256) gemm_tc_kernel(
    const void* __restrict__ Xin, int N, int apply_relu, int layer)
{
    extern __shared__ char smem[];
    __half* As_h = (__half*)(smem + SM_AH);
    __half* Ws_h = (__half*)(smem + SM_WH);

    int tid = threadIdx.x;
    int m0  = blockIdx.x * 64;

    // ---- load W^T into padded smem: 128 rows x 256B
    {
        const uint4* gh = (const uint4*)g_Wht[layer];
        #pragma unroll
        for (int r = 0; r < 8; r++) {
            int idx = tid + r * 256;
            int row = idx >> 4, ch = idx & 15;
            ((uint4*)((char*)Ws_h + row * AROW * 2))[ch] = gh[row * 16 + ch];
        }
    }

    // ---- load A tile
    if (MODE == 0) {
        const float* X = (const float*)Xin;
        #pragma unroll
        for (int r = 0; r < 8; r++) {
            int idx = tid + r * 256;
            int row = idx >> 5, c4 = idx & 31;
            int gm = m0 + row;
            float4 v = make_float4(0.f, 0.f, 0.f, 0.f);
            if (gm < N) v = *(const float4*)(X + (size_t)gm * D + c4 * 4);
            if (apply_relu) {
                v.x = fmaxf(v.x, 0.f); v.y = fmaxf(v.y, 0.f);
                v.z = fmaxf(v.z, 0.f); v.w = fmaxf(v.w, 0.f);
            }
            __half2* ph = (__half2*)(As_h + row * AROW + c4 * 4);
            ph[0] = __floats2half2_rn(v.x, v.y);
            ph[1] = __floats2half2_rn(v.z, v.w);
        }
    } else {
        // fp16 input: 64 rows x 256B
        const uint4* X = (const uint4*)Xin;     // 16 uint4 per row
        const __half2 z2 = __half2(__half(0.f), __half(0.f));
        #pragma unroll
        for (int r = 0; r < 4; r++) {
            int idx = tid + r * 256;            // 1024 uint4 slots
            int row = idx >> 4, ch = idx & 15;
            int gm = m0 + row;
            uint4 v = make_uint4(0u, 0u, 0u, 0u);
            if (gm < N) v = X[(size_t)gm * 16 + ch];
            if (apply_relu) {
                __half2* h = (__half2*)&v;
                h[0] = __hmax2(h[0], z2); h[1] = __hmax2(h[1], z2);
                h[2] = __hmax2(h[2], z2); h[3] = __hmax2(h[3], z2);
            }
            *(uint4*)(As_h + row * AROW + ch * 8) = v;
        }
    }
    __syncthreads();

    int wid  = tid >> 5, lane = tid & 31;
    int wm   = wid & 1, wn = wid >> 1;
    int g    = lane >> 2;
    int kk   = (lane & 3) * 2;

    float acc[2][4][4];
    #pragma unroll
    for (int mt = 0; mt < 2; mt++)
        #pragma unroll
        for (int nt = 0; nt < 4; nt++)
            #pragma unroll
            for (int r = 0; r < 4; r++) acc[mt][nt][r] = 0.f;

    #pragma unroll
    for (int ks = 0; ks < 8; ks++) {
        int k0 = ks * 16;
        unsigned ah[2][4];
        #pragma unroll
        for (int mt = 0; mt < 2; mt++) {
            int r0 = wm * 32 + mt * 16 + g;
            ah[mt][0] = *(const unsigned*)(As_h + r0 * AROW + k0 + kk);
            ah[mt][1] = *(const unsigned*)(As_h + (r0 + 8) * AROW + k0 + kk);
            ah[mt][2] = *(const unsigned*)(As_h + r0 * AROW + k0 + kk + 8);
            ah[mt][3] = *(const unsigned*)(As_h + (r0 + 8) * AROW + k0 + kk + 8);
        }
        #pragma unroll
        for (int nt = 0; nt < 4; nt++) {
            int c = wn * 32 + nt * 8 + g;
            unsigned bh0 = *(const unsigned*)(Ws_h + c * AROW + k0 + kk);
            unsigned bh1 = *(const unsigned*)(Ws_h + c * AROW + k0 + kk + 8);
            #pragma unroll
            for (int mt = 0; mt < 2; mt++) {
                float* a = acc[mt][nt];
                mma_f16(a[0], a[1], a[2], a[3],
                        ah[mt][0], ah[mt][1], ah[mt][2], ah[mt][3], bh0, bh1);
            }
        }
    }

    // ---- epilogue: store fp16 (no dinv — applied in aggregation)
    #pragma unroll
    for (int mt = 0; mt < 2; mt++) {
        int r0 = m0 + wm * 32 + mt * 16 + g;
        int r1 = r0 + 8;
        #pragma unroll
        for (int nt = 0; nt < 4; nt++) {
            int col = wn * 32 + nt * 8 + (lane & 3) * 2;
            float* a = acc[mt][nt];
            if (r0 < N)
                *(__half2*)(g_hh + (size_t)r0 * D + col) =
                    __floats2half2_rn(a[0], a[1]);
            if (r1 < N)
                *(__half2*)(g_hh + (size_t)r1 * D + col) =
                    __floats2half2_rn(a[2], a[3]);
        }
    }
}

// ---------------------------------------------------------------- Aggregate
// out[i] = dinv[i] * ( h[i]*dinv[i] + sum_e h[col[e]]*dinv[col[e]] ) + b
// one warp per node; lane handles 4 halves (8B) of the 256B fp16 row.
__device__ __forceinline__ void fma_h4(float4& acc, uint2 v, float s) {
    float2 a = __half22float2(*(__half2*)&v.x);
    float2 b = __half22float2(*(__half2*)&v.y);
    acc.x = fmaf(a.x, s, acc.x); acc.y = fmaf(a.y, s, acc.y);
    acc.z = fmaf(b.x, s, acc.z); acc.w = fmaf(b.y, s, acc.w);
}

template<typename OutT>
__global__ void __launch_bounds__(256) agg_kernel(
    const float* __restrict__ bias, OutT* __restrict__ out, int N,
    int zero_first)
{
    int w    = (int)((blockIdx.x * blockDim.x + threadIdx.x) >> 5);
    int lane = threadIdx.x & 31;
    if (w >= N) return;

    if (zero_first && w == 0) {   // final layer: out[0] = zeros
        if (sizeof(OutT) == 4)
            ((float4*)out)[lane] = make_float4(0.f, 0.f, 0.f, 0.f);
        else
            ((uint2*)out)[lane] = make_uint2(0u, 0u);
        return;
    }

    const uint2* H2 = (const uint2*)g_hh;   // 32 uint2 per row
    float dv = g_dinv[w];
    float4 acc = make_float4(0.f, 0.f, 0.f, 0.f);
    fma_h4(acc, H2[(size_t)w * 32 + lane], dv);   // self-loop: h[i]*dinv[i]
    int beg = g_off[w], end = g_end[w];

    int e = beg;
    for (; e + 3 < end; e += 4) {
        int s0 = g_col[e],     s1 = g_col[e + 1];
        int s2 = g_col[e + 2], s3 = g_col[e + 3];
        uint2 v0 = H2[(size_t)s0 * 32 + lane];
        uint2 v1 = H2[(size_t)s1 * 32 + lane];
        uint2 v2 = H2[(size_t)s2 * 32 + lane];
        uint2 v3 = H2[(size_t)s3 * 32 + lane];
        float d0 = g_dinv[s0], d1 = g_dinv[s1];
        float d2 = g_dinv[s2], d3 = g_dinv[s3];
        fma_h4(acc, v0, d0); fma_h4(acc, v1, d1);
        fma_h4(acc, v2, d2); fma_h4(acc, v3, d3);
    }
    for (; e < end; e++) {
        int s0 = g_col[e];
        fma_h4(acc, H2[(size_t)s0 * 32 + lane], g_dinv[s0]);
    }

    float4 bb = ((const float4*)bias)[lane];
    float4 o;
    o.x = fmaf(acc.x, dv, bb.x);
    o.y = fmaf(acc.y, dv, bb.y);
    o.z = fmaf(acc.z, dv, bb.z);
    o.w = fmaf(acc.w, dv, bb.w);
    if (sizeof(OutT) == 4) {
        ((float4*)out)[(size_t)w * 32 + lane] = o;
    } else {
        uint2 p;
        *(__half2*)&p.x = __floats2half2_rn(o.x, o.y);
        *(__half2*)&p.y = __floats2half2_rn(o.z, o.w);
        ((uint2*)out)[(size_t)w * 32 + lane] = p;
    }
}

// ---------------------------------------------------------------- launch
extern "C" void kernel_launch(void* const* d_in, const int* in_sizes, int n_in,
                              void* d_out, int out_size)
{
    const float* emb = (const float*)d_in[0];
    const float* W1  = (const float*)d_in[1];
    const float* b1  = (const float*)d_in[2];
    const float* W2  = (const float*)d_in[3];
    const float* b2  = (const float*)d_in[4];
    const float* W3  = (const float*)d_in[5];
    const float* b3  = (const float*)d_in[6];
    const void*  ei  = d_in[7];

    int N = in_sizes[0] / D;
    int E = in_sizes[7] / 2;
    float* out = (float*)d_out;

    void* p;
    cudaGetSymbolAddress(&p, g_xh);  __half* Xh = (__half*)p;

    static cudaStream_t s2 = nullptr;
    static cudaEvent_t evFork = nullptr, evJoin = nullptr;
    if (!s2) {
        cudaFuncSetAttribute(gemm_tc_kernel<0>,
            cudaFuncAttributeMaxDynamicSharedMemorySize, SM_TOT);
        cudaFuncSetAttribute(gemm_tc_kernel<1>,
            cudaFuncAttributeMaxDynamicSharedMemorySize, SM_TOT);
        cudaStreamCreateWithFlags(&s2, cudaStreamNonBlocking);
        cudaEventCreateWithFlags(&evFork, cudaEventDisableTiming);
        cudaEventCreateWithFlags(&evJoin, cudaEventDisableTiming);
    }

    int tb = 256;
    int nblk = (N + 255) / 256;
    int gemm_grid = (N + 63) / 64;
    int agg_grid  = (N + 7) / 8;

    // ---- fork: weight convert + layer-1 GEMM on s2 (independent of CSR)
    cudaEventRecord(evFork, 0);
    cudaStreamWaitEvent(s2, evFork, 0);
    wsplit_kernel<<<(3 * D * D + tb - 1) / tb, tb, 0, s2>>>(W1, W2, W3);
    gemm_tc_kernel<0><<<gemm_grid, 256, SM_TOT, s2>>>(emb, N, 0, 0);
    cudaEventRecord(evJoin, s2);

    // ---- CSR build on default stream (concurrent with s2)
    init_kernel<<<nblk, 256>>>((const int*)ei, N);
    count_kernel<<<(E + tb - 1) / tb, tb>>>(ei, E);
    offsets_kernel<<<nblk, 256>>>(N);
    fill_kernel<<<(E + tb - 1) / tb, tb>>>(ei, E);

    // ---- join, then the dependent chain
    cudaStreamWaitEvent(0, evJoin, 0);
    agg_kernel<__half><<<agg_grid, 256>>>(b1, Xh, N, 0);
    gemm_tc_kernel<1><<<gemm_grid, 256, SM_TOT>>>(Xh, N, 1, 1);
    agg_kernel<__half><<<agg_grid, 256>>>(b2, Xh, N, 0);
    gemm_tc_kernel<1><<<gemm_grid, 256, SM_TOT>>>(Xh, N, 1, 2);
    agg_kernel<float><<<agg_grid, 256>>>(b3, out, N, 1);
}